// round 1
// baseline (speedup 1.0000x reference)
#include <cuda_runtime.h>

// Bilinear 2x upsample, NHWC f32.
// in : (8, 256, 256, 64)
// out: (8, 512, 512, 64)
// half_pixel coords with clamp at 0 (matches reference _coords).

static constexpr int IN_H  = 256;
static constexpr int IN_W  = 256;
static constexpr int OUT_H = 512;
static constexpr int OUT_W = 512;
static constexpr int C     = 64;
static constexpr int CV    = C / 4;   // float4 vectors per pixel = 16

__global__ __launch_bounds__(256)
void bilerp2x_kernel(const float4* __restrict__ in, float4* __restrict__ out) {
    // One thread = one float4 of one output pixel.
    // tid within a row: ox in [0,512), cvec in [0,16)
    int tid  = blockIdx.x * blockDim.x + threadIdx.x;   // 0 .. 512*16-1
    int cvec = tid & (CV - 1);
    int ox   = tid >> 4;
    int oy   = blockIdx.y;
    int b    = blockIdx.z;

    // half-pixel source coords, clamped below at 0 (scale = 0.5 exactly)
    float sx = fmaxf((ox + 0.5f) * 0.5f - 0.5f, 0.0f);
    float sy = fmaxf((oy + 0.5f) * 0.5f - 0.5f, 0.0f);
    int x0 = (int)sx;                 // sx >= 0, so trunc == floor
    int y0 = (int)sy;
    int x1 = min(x0 + 1, IN_W - 1);
    int y1 = min(y0 + 1, IN_H - 1);
    float dx = sx - (float)x0;
    float dy = sy - (float)y0;

    float w00 = (1.0f - dx) * (1.0f - dy);
    float w10 = dx * (1.0f - dy);
    float w01 = (1.0f - dx) * dy;
    float w11 = dx * dy;

    // float4-unit indices: ((b*IN_H + y)*IN_W + x)*CV + cvec
    long rowb0 = ((long)(b * IN_H + y0) * IN_W) * CV + cvec;
    long rowb1 = ((long)(b * IN_H + y1) * IN_W) * CV + cvec;

    float4 p00 = in[rowb0 + (long)x0 * CV];
    float4 p10 = in[rowb0 + (long)x1 * CV];
    float4 p01 = in[rowb1 + (long)x0 * CV];
    float4 p11 = in[rowb1 + (long)x1 * CV];

    float4 r;
    r.x = p00.x * w00 + p10.x * w10 + p01.x * w01 + p11.x * w11;
    r.y = p00.y * w00 + p10.y * w10 + p01.y * w01 + p11.y * w11;
    r.z = p00.z * w00 + p10.z * w10 + p01.z * w01 + p11.z * w11;
    r.w = p00.w * w00 + p10.w * w10 + p01.w * w01 + p11.w * w11;

    long oidx = ((long)(b * OUT_H + oy) * OUT_W + ox) * CV + cvec;
    out[oidx] = r;
}

extern "C" void kernel_launch(void* const* d_in, const int* in_sizes, int n_in,
                              void* d_out, int out_size) {
    const float4* in  = (const float4*)d_in[0];
    float4*       out = (float4*)d_out;

    dim3 block(256);
    dim3 grid((OUT_W * CV) / 256, OUT_H, 8);   // 32 x 512 x 8
    bilerp2x_kernel<<<grid, block>>>(in, out);
}

// round 2
// speedup vs baseline: 1.3923x; 1.3923x over previous
#include <cuda_runtime.h>

// Bilinear 2x upsample, NHWC f32, 2x2-output-per-thread formulation.
// in : (8, 256, 256, 64), out: (8, 512, 512, 64)
// Output pixels (2i+1, 2i+2) read exactly input cols (i, i+1) with dx=0.25/0.75.
// Same separably in y. Edges handled by clamped duplicate taps.

static constexpr int IN_H  = 256;
static constexpr int IN_W  = 256;
static constexpr int OUT_H = 512;
static constexpr int OUT_W = 512;
static constexpr int CV    = 16;   // float4 vectors per pixel (C=64)

__device__ __forceinline__ float4 lerp4(float4 a, float4 b, float wb) {
    // a*(1-wb) + b*wb
    float wa = 1.0f - wb;
    float4 r;
    r.x = a.x * wa + b.x * wb;
    r.y = a.y * wa + b.y * wb;
    r.z = a.z * wa + b.z * wb;
    r.w = a.w * wa + b.w * wb;
    return r;
}

__global__ __launch_bounds__(256)
void bilerp2x_q_kernel(const float4* __restrict__ in, float4* __restrict__ out) {
    int cvec = threadIdx.x;                      // 0..15
    int i    = blockIdx.x * 16 + threadIdx.y;    // column group, 0..256
    int j    = blockIdx.y;                       // row group, 0..256
    int b    = blockIdx.z;
    if (i > 256) return;

    int ii = i - 1;                              // input col pair base
    int jj = j - 1;                              // input row pair base
    int x_lo = max(ii, 0);
    int x_hi = min(ii + 1, IN_W - 1);
    int y_lo = max(jj, 0);
    int y_hi = min(jj + 1, IN_H - 1);

    long in_b = (long)b * IN_H * IN_W * CV;
    const float4* r0 = in + in_b + (long)(y_lo * IN_W) * CV + cvec;
    const float4* r1 = in + in_b + (long)(y_hi * IN_W) * CV + cvec;

    float4 p00 = __ldg(r0 + (long)x_lo * CV);
    float4 p01 = __ldg(r0 + (long)x_hi * CV);
    float4 p10 = __ldg(r1 + (long)x_lo * CV);
    float4 p11 = __ldg(r1 + (long)x_hi * CV);

    // horizontal lerps: ox_a = 2*ii+1 -> dx=0.25 ; ox_b = 2*ii+2 -> dx=0.75
    float4 ta = lerp4(p00, p01, 0.25f);
    float4 tb = lerp4(p00, p01, 0.75f);
    float4 ba = lerp4(p10, p11, 0.25f);
    float4 bb = lerp4(p10, p11, 0.75f);

    int ox_a = 2 * i - 1;     // = 2*ii+1
    int ox_b = 2 * i;         // = 2*ii+2
    int oy_a = 2 * j - 1;
    int oy_b = 2 * j;

    bool wxa = (i >= 1);
    bool wxb = (i <= 255);
    bool wya = (j >= 1);
    bool wyb = (j <= 255);

    long out_b = (long)b * OUT_H * OUT_W * CV + cvec;

    if (wya) {  // oy_a, dy = 0.25
        long row = out_b + (long)(oy_a * OUT_W) * CV;
        if (wxa) { float4 v = lerp4(ta, ba, 0.25f); __stcs(&out[row + (long)ox_a * CV], v); }
        if (wxb) { float4 v = lerp4(tb, bb, 0.25f); __stcs(&out[row + (long)ox_b * CV], v); }
    }
    if (wyb) {  // oy_b, dy = 0.75
        long row = out_b + (long)(oy_b * OUT_W) * CV;
        if (wxa) { float4 v = lerp4(ta, ba, 0.75f); __stcs(&out[row + (long)ox_a * CV], v); }
        if (wxb) { float4 v = lerp4(tb, bb, 0.75f); __stcs(&out[row + (long)ox_b * CV], v); }
    }
}

extern "C" void kernel_launch(void* const* d_in, const int* in_sizes, int n_in,
                              void* d_out, int out_size) {
    const float4* in  = (const float4*)d_in[0];
    float4*       out = (float4*)d_out;

    dim3 block(16, 16);                 // tx = cvec, ty = column group within block
    dim3 grid(17, 257, 8);              // 17*16=272 >= 257 column groups; 257 row groups; 8 batches
    bilerp2x_q_kernel<<<grid, block>>>(in, out);
}